// round 2
// baseline (speedup 1.0000x reference)
#include <cuda_runtime.h>

// ============================================================================
// AdaMLP: gathered-expert 2-layer MLP.
//   slots:   (1024, 256) f32   (B*K flattened)
//   w1:      (64, 256, 1024) f32
//   b1:      (64, 1024) f32
//   w2:      (64, 1024, 256) f32
//   b2:      (64, 256) f32
//   indices: (1024,) int64 (or int32 depending on jax x64 config — auto-detect)
//   out:     (1024, 256) f32
//
// Strategy: group slots by expert so each expert's 2MB of weights is streamed
// exactly once. GEMMs use fp32x2 packed FMA (FFMA2) with slot-pairs in the
// two lanes. R-dim of GEMM2 split 4 ways into partials for occupancy;
// deterministic reduce adds partials + b2.
// ============================================================================

typedef unsigned long long u64;

#define NEXP 64
#define NSLOT 1024
#define DIM 256
#define RDIM 1024
#define SC 32      // slots per chunk
#define PAD 36     // smem row stride in floats (32 + 4 pad, keeps 16B align)

__device__ int   g_cnt[NEXP];
__device__ int   g_list[NEXP * NSLOT];
__device__ int   g_slot_e[NSLOT];
__device__ float g_H[NSLOT * RDIM];          // 4 MB hidden (post-ReLU)
__device__ float g_P[4 * NSLOT * DIM];       // 4 MB partial outputs (4 r-segments)

__device__ __forceinline__ u64 pack2(float x, float y) {
    u64 r;
    asm("mov.b64 %0, {%1,%2};" : "=l"(r) : "f"(x), "f"(y));
    return r;
}
__device__ __forceinline__ void fma2(u64& d, u64 a, u64 b) {
    asm("fma.rn.f32x2 %0, %1, %2, %0;" : "+l"(d) : "l"(a), "l"(b));
}
__device__ __forceinline__ float2 unpack2(u64 v) {
    float lo, hi;
    asm("mov.b64 {%0,%1}, %2;" : "=f"(lo), "=f"(hi) : "l"(v));
    return make_float2(lo, hi);
}

// ----------------------------------------------------------------------------
// Group slots by expert. One CTA, 1024 threads.
// Detect int64 vs int32 indices: int64 little-endian with values in [0,64)
// has all odd 32-bit words zero. First 512 pairs (4KB) are safely readable
// under either dtype.
// ----------------------------------------------------------------------------
__global__ void group_kernel(const int* __restrict__ idx32) {
    int tid = threadIdx.x;
    __shared__ int s_flag;
    if (tid == 0) s_flag = 0;
    if (tid < NEXP) g_cnt[tid] = 0;
    __syncthreads();
    if (tid < 512) {
        if (idx32[2 * tid + 1] != 0) atomicOr(&s_flag, 1);
    }
    __syncthreads();
    int e = s_flag ? idx32[tid] : idx32[2 * tid];
    e &= (NEXP - 1);
    g_slot_e[tid] = e;
    int p = atomicAdd(&g_cnt[e], 1);
    g_list[e * NSLOT + p] = tid;
}

// ----------------------------------------------------------------------------
// GEMM1: H[s, r] = relu( sum_d slots[s,d] * w1[e,d,r] + b1[e,r] )
// grid (4 r-tiles of 256 cols, 64 experts), 128 threads, 2 cols/thread.
// Slots chunked SC=32, stored transposed in smem so slot-pairs pack into
// f32x2 lanes and LDS.128 fetches 4 slot values at once (broadcast).
// ----------------------------------------------------------------------------
__global__ __launch_bounds__(128) void gemm1_kernel(
    const float* __restrict__ slots,
    const float* __restrict__ w1,
    const float* __restrict__ b1)
{
    int e = blockIdx.y;
    int n = g_cnt[e];
    if (n == 0) return;
    int r0 = blockIdx.x * 256;
    int c  = threadIdx.x * 2;

    __shared__ __align__(16) float ssl[DIM * PAD];
    __shared__ int sid[SC];

    const float* Wp = w1 + (size_t)e * (DIM * RDIM) + r0 + c;
    float2 bb = *(const float2*)(b1 + (size_t)e * RDIM + r0 + c);

    for (int s0 = 0; s0 < n; s0 += SC) {
        int sc = min(SC, n - s0);
        if (threadIdx.x < sc) sid[threadIdx.x] = g_list[e * NSLOT + s0 + threadIdx.x];
        __syncthreads();
        for (int t = threadIdx.x; t < sc * DIM; t += 128) {
            int j = t >> 8, d = t & 255;
            ssl[d * PAD + j] = slots[(size_t)sid[j] * DIM + d];
        }
        __syncthreads();

        u64 acc[16][2];
#pragma unroll
        for (int p = 0; p < 16; p++) { acc[p][0] = 0ull; acc[p][1] = 0ull; }

#pragma unroll 8
        for (int d = 0; d < DIM; d++) {
            float2 w = *(const float2*)(Wp + (size_t)d * RDIM);
            u64 wx = pack2(w.x, w.x);
            u64 wy = pack2(w.y, w.y);
            const ulonglong2* sp = (const ulonglong2*)(ssl + d * PAD);
#pragma unroll
            for (int q = 0; q < 8; q++) {
                ulonglong2 s = sp[q];          // slots 4q..4q+3 (broadcast)
                fma2(acc[2 * q][0], s.x, wx);
                fma2(acc[2 * q][1], s.x, wy);
                fma2(acc[2 * q + 1][0], s.y, wx);
                fma2(acc[2 * q + 1][1], s.y, wy);
            }
        }

#pragma unroll
        for (int p = 0; p < 16; p++) {
            float2 a0 = unpack2(acc[p][0]);   // col c   : {slot 2p, slot 2p+1}
            float2 a1 = unpack2(acc[p][1]);   // col c+1 : {slot 2p, slot 2p+1}
            int j0 = 2 * p, j1 = 2 * p + 1;
            if (j0 < sc) {
                float2 hv = make_float2(fmaxf(a0.x + bb.x, 0.0f),
                                        fmaxf(a1.x + bb.y, 0.0f));
                *(float2*)(g_H + (size_t)sid[j0] * RDIM + r0 + c) = hv;
            }
            if (j1 < sc) {
                float2 hv = make_float2(fmaxf(a0.y + bb.x, 0.0f),
                                        fmaxf(a1.y + bb.y, 0.0f));
                *(float2*)(g_H + (size_t)sid[j1] * RDIM + r0 + c) = hv;
            }
        }
        __syncthreads();
    }
}

// ----------------------------------------------------------------------------
// GEMM2 (partial): P[seg, s, dc] = sum_{r in seg} H[s, r] * w2[e, r, dc]
// grid (4 r-segments of 256, 64 experts), 128 threads, 2 cols/thread (=DIM).
// ----------------------------------------------------------------------------
__global__ __launch_bounds__(128) void gemm2_kernel(const float* __restrict__ w2)
{
    int e = blockIdx.y;
    int n = g_cnt[e];
    if (n == 0) return;
    int seg   = blockIdx.x;
    int rbase = seg * 256;
    int c     = threadIdx.x * 2;

    __shared__ __align__(16) float hs[256 * PAD];
    __shared__ int sid[SC];

    const float* Wp = w2 + (size_t)e * (RDIM * DIM) + (size_t)rbase * DIM + c;
    float* Pp = g_P + (size_t)seg * (NSLOT * DIM);

    for (int s0 = 0; s0 < n; s0 += SC) {
        int sc = min(SC, n - s0);
        if (threadIdx.x < sc) sid[threadIdx.x] = g_list[e * NSLOT + s0 + threadIdx.x];
        __syncthreads();
        for (int t = threadIdx.x; t < sc * 256; t += 128) {
            int j = t >> 8, r = t & 255;
            hs[r * PAD + j] = g_H[(size_t)sid[j] * RDIM + rbase + r];
        }
        __syncthreads();

        u64 acc[16][2];
#pragma unroll
        for (int p = 0; p < 16; p++) { acc[p][0] = 0ull; acc[p][1] = 0ull; }

#pragma unroll 8
        for (int r = 0; r < 256; r++) {
            float2 w = *(const float2*)(Wp + (size_t)r * DIM);
            u64 wx = pack2(w.x, w.x);
            u64 wy = pack2(w.y, w.y);
            const ulonglong2* sp = (const ulonglong2*)(hs + r * PAD);
#pragma unroll
            for (int q = 0; q < 8; q++) {
                ulonglong2 s = sp[q];
                fma2(acc[2 * q][0], s.x, wx);
                fma2(acc[2 * q][1], s.x, wy);
                fma2(acc[2 * q + 1][0], s.y, wx);
                fma2(acc[2 * q + 1][1], s.y, wy);
            }
        }

#pragma unroll
        for (int p = 0; p < 16; p++) {
            float2 a0 = unpack2(acc[p][0]);
            float2 a1 = unpack2(acc[p][1]);
            int j0 = 2 * p, j1 = 2 * p + 1;
            if (j0 < sc) {
                *(float2*)(Pp + (size_t)sid[j0] * DIM + c) = make_float2(a0.x, a1.x);
            }
            if (j1 < sc) {
                *(float2*)(Pp + (size_t)sid[j1] * DIM + c) = make_float2(a0.y, a1.y);
            }
        }
        __syncthreads();
    }
}

// ----------------------------------------------------------------------------
// Reduce: out[s, dc] = sum_seg P[seg, s, dc] + b2[e(s), dc]
// ----------------------------------------------------------------------------
__global__ void reduce_kernel(const float* __restrict__ b2, float* __restrict__ out)
{
    int slot = blockIdx.x;
    int c    = threadIdx.x;
    int e    = g_slot_e[slot];
    size_t o = (size_t)slot * DIM + c;
    const size_t SEG = (size_t)NSLOT * DIM;
    float v = g_P[o] + g_P[SEG + o] + g_P[2 * SEG + o] + g_P[3 * SEG + o]
            + b2[(size_t)e * DIM + c];
    out[o] = v;
}

// ----------------------------------------------------------------------------
extern "C" void kernel_launch(void* const* d_in, const int* in_sizes, int n_in,
                              void* d_out, int out_size)
{
    const float* slots = (const float*)d_in[0];
    const float* w1    = (const float*)d_in[1];
    const float* b1    = (const float*)d_in[2];
    const float* w2    = (const float*)d_in[3];
    const float* b2    = (const float*)d_in[4];
    const int*   idx   = (const int*)d_in[5];
    float* out = (float*)d_out;

    group_kernel<<<1, 1024>>>(idx);
    gemm1_kernel<<<dim3(4, NEXP), 128>>>(slots, w1, b1);
    gemm2_kernel<<<dim3(4, NEXP), 128>>>(w2);
    reduce_kernel<<<NSLOT, DIM>>>(b2, out);
}

// round 4
// speedup vs baseline: 1.3807x; 1.3807x over previous
#include <cuda_runtime.h>

// ============================================================================
// AdaMLP: gathered-expert 2-layer MLP (B*K=1024 slots, 64 experts, 256->1024->256).
// R2: latency-oriented restructure of the FFMA2 grouped-GEMM path.
//   - 16-slot chunks (acc = 16 fp32 = 8 x f32x2 regs/thread, no spills)
//   - 1 output col/thread, 128-col r-tiles, grid (8,64) = 512 CTAs -> ~14 warps/SM
//   - staged unroll-8 weight LDG.32 (8 loads in flight/thread)
//   - vectorized float4 reduce
// ============================================================================

typedef unsigned long long u64;

#define NEXP 64
#define NSLOT 1024
#define DIM 256
#define RDIM 1024
#define SC 16          // slots per chunk
#define SPAD 20        // smem row stride in floats (16 + 4; 80B, 16B-aligned)

__device__ int   g_cnt[NEXP];
__device__ int   g_list[NEXP * NSLOT];
__device__ int   g_slot_e[NSLOT];
__device__ float g_H[NSLOT * RDIM];          // 4 MB hidden (post-ReLU)
__device__ float g_P[4 * NSLOT * DIM];       // 4 MB partial outputs (4 r-segments)

__device__ __forceinline__ u64 pack2(float x, float y) {
    u64 r;
    asm("mov.b64 %0, {%1,%2};" : "=l"(r) : "f"(x), "f"(y));
    return r;
}
__device__ __forceinline__ void fma2(u64& d, u64 a, u64 b) {
    asm("fma.rn.f32x2 %0, %1, %2, %0;" : "+l"(d) : "l"(a), "l"(b));
}
__device__ __forceinline__ float2 unpack2(u64 v) {
    float lo, hi;
    asm("mov.b64 {%0,%1}, %2;" : "=f"(lo), "=f"(hi) : "l"(v));
    return make_float2(lo, hi);
}

// ----------------------------------------------------------------------------
// Group slots by expert. One CTA, 1024 threads.
// int64-vs-int32 indices auto-detect (odd 32-bit words all zero => int64).
// ----------------------------------------------------------------------------
__global__ void group_kernel(const int* __restrict__ idx32) {
    int tid = threadIdx.x;
    __shared__ int s_flag;
    if (tid == 0) s_flag = 0;
    if (tid < NEXP) g_cnt[tid] = 0;
    __syncthreads();
    if (tid < 512) {
        if (idx32[2 * tid + 1] != 0) atomicOr(&s_flag, 1);
    }
    __syncthreads();
    int e = s_flag ? idx32[tid] : idx32[2 * tid];
    e &= (NEXP - 1);
    g_slot_e[tid] = e;
    int p = atomicAdd(&g_cnt[e], 1);
    g_list[e * NSLOT + p] = tid;
}

// ----------------------------------------------------------------------------
// GEMM1: H[s, r] = relu( sum_d slots[s,d] * w1[e,d,r] + b1[e,r] )
// grid (8 r-tiles of 128, 64 experts), 128 threads, 1 col/thread.
// ----------------------------------------------------------------------------
__global__ __launch_bounds__(128) void gemm1_kernel(
    const float* __restrict__ slots,
    const float* __restrict__ w1,
    const float* __restrict__ b1)
{
    int e = blockIdx.y;
    int n = g_cnt[e];
    if (n == 0) return;
    int c = blockIdx.x * 128 + threadIdx.x;
    int tid = threadIdx.x;

    __shared__ __align__(16) float ssl[DIM * SPAD];
    __shared__ int sid[SC];

    const float* Wp = w1 + (size_t)e * (DIM * RDIM) + c;
    float b = b1[(size_t)e * RDIM + c];

    for (int s0 = 0; s0 < n; s0 += SC) {
        int sc = min(SC, n - s0);
        if (tid < SC) sid[tid] = (tid < sc) ? g_list[e * NSLOT + s0 + tid] : 0;
        __syncthreads();
#pragma unroll
        for (int j = 0; j < SC; j++) {
            int valid = j < sc;
            int sj = sid[j];
            for (int d = tid; d < DIM; d += 128) {
                float v = 0.0f;
                if (valid) v = slots[(size_t)sj * DIM + d];
                ssl[d * SPAD + j] = v;
            }
        }
        __syncthreads();

        u64 acc[8];
#pragma unroll
        for (int p = 0; p < 8; p++) acc[p] = 0ull;

        for (int dd = 0; dd < DIM; dd += 8) {
            float wreg[8];
#pragma unroll
            for (int i = 0; i < 8; i++) wreg[i] = Wp[(size_t)(dd + i) * RDIM];
#pragma unroll
            for (int i = 0; i < 8; i++) {
                u64 ww = pack2(wreg[i], wreg[i]);
                const ulonglong2* sp = (const ulonglong2*)(ssl + (dd + i) * SPAD);
#pragma unroll
                for (int q = 0; q < 4; q++) {
                    ulonglong2 s = sp[q];
                    fma2(acc[2 * q], s.x, ww);       // slots 4q, 4q+1
                    fma2(acc[2 * q + 1], s.y, ww);   // slots 4q+2, 4q+3
                }
            }
        }

#pragma unroll
        for (int q = 0; q < 4; q++) {
            float2 a0 = unpack2(acc[2 * q]);
            float2 a1 = unpack2(acc[2 * q + 1]);
            int j = 4 * q;
            if (j + 0 < sc) g_H[(size_t)sid[j + 0] * RDIM + c] = fmaxf(a0.x + b, 0.0f);
            if (j + 1 < sc) g_H[(size_t)sid[j + 1] * RDIM + c] = fmaxf(a0.y + b, 0.0f);
            if (j + 2 < sc) g_H[(size_t)sid[j + 2] * RDIM + c] = fmaxf(a1.x + b, 0.0f);
            if (j + 3 < sc) g_H[(size_t)sid[j + 3] * RDIM + c] = fmaxf(a1.y + b, 0.0f);
        }
        __syncthreads();
    }
}

// ----------------------------------------------------------------------------
// GEMM2 (partial): P[seg, s, dc] = sum_{r in seg} H[s, r] * w2[e, r, dc]
// grid (4 segs * 2 dc-tiles, 64 experts), 128 threads, 1 col/thread.
// ----------------------------------------------------------------------------
__global__ __launch_bounds__(128) void gemm2_kernel(const float* __restrict__ w2)
{
    int e = blockIdx.y;
    int n = g_cnt[e];
    if (n == 0) return;
    int seg   = blockIdx.x >> 1;          // 0..3 -> r segment of 256
    int rbase = seg * 256;
    int c     = (blockIdx.x & 1) * 128 + threadIdx.x;   // 0..255 output col
    int tid = threadIdx.x;

    __shared__ __align__(16) float hs[256 * SPAD];
    __shared__ int sid[SC];

    const float* Wp = w2 + (size_t)e * (RDIM * DIM) + (size_t)rbase * DIM + c;
    float* Pp = g_P + (size_t)seg * (NSLOT * DIM);

    for (int s0 = 0; s0 < n; s0 += SC) {
        int sc = min(SC, n - s0);
        if (tid < SC) sid[tid] = (tid < sc) ? g_list[e * NSLOT + s0 + tid] : 0;
        __syncthreads();
#pragma unroll
        for (int j = 0; j < SC; j++) {
            int valid = j < sc;
            int sj = sid[j];
            for (int r = tid; r < 256; r += 128) {
                float v = 0.0f;
                if (valid) v = g_H[(size_t)sj * RDIM + rbase + r];
                hs[r * SPAD + j] = v;
            }
        }
        __syncthreads();

        u64 acc[8];
#pragma unroll
        for (int p = 0; p < 8; p++) acc[p] = 0ull;

        for (int rr = 0; rr < 256; rr += 8) {
            float wreg[8];
#pragma unroll
            for (int i = 0; i < 8; i++) wreg[i] = Wp[(size_t)(rr + i) * DIM];
#pragma unroll
            for (int i = 0; i < 8; i++) {
                u64 ww = pack2(wreg[i], wreg[i]);
                const ulonglong2* sp = (const ulonglong2*)(hs + (rr + i) * SPAD);
#pragma unroll
                for (int q = 0; q < 4; q++) {
                    ulonglong2 s = sp[q];
                    fma2(acc[2 * q], s.x, ww);
                    fma2(acc[2 * q + 1], s.y, ww);
                }
            }
        }

#pragma unroll
        for (int q = 0; q < 4; q++) {
            float2 a0 = unpack2(acc[2 * q]);
            float2 a1 = unpack2(acc[2 * q + 1]);
            int j = 4 * q;
            if (j + 0 < sc) Pp[(size_t)sid[j + 0] * DIM + c] = a0.x;
            if (j + 1 < sc) Pp[(size_t)sid[j + 1] * DIM + c] = a0.y;
            if (j + 2 < sc) Pp[(size_t)sid[j + 2] * DIM + c] = a1.x;
            if (j + 3 < sc) Pp[(size_t)sid[j + 3] * DIM + c] = a1.y;
        }
        __syncthreads();
    }
}

// ----------------------------------------------------------------------------
// Reduce: out[s, :] = sum_seg P[seg, s, :] + b2[e(s), :]   (float4 vectorized)
// ----------------------------------------------------------------------------
__global__ void reduce_kernel(const float* __restrict__ b2, float* __restrict__ out)
{
    int t = blockIdx.x * 256 + threadIdx.x;   // float4 index, 65536 total
    int slot = t >> 6;                        // 64 float4 per slot
    int e = g_slot_e[slot];
    const float4* P = (const float4*)g_P;
    const int SEG = NSLOT * DIM / 4;          // 65536
    float4 v0 = P[t];
    float4 v1 = P[SEG + t];
    float4 v2 = P[2 * SEG + t];
    float4 v3 = P[3 * SEG + t];
    float4 bb = ((const float4*)b2)[e * 64 + (t & 63)];
    float4 r;
    r.x = v0.x + v1.x + v2.x + v3.x + bb.x;
    r.y = v0.y + v1.y + v2.y + v3.y + bb.y;
    r.z = v0.z + v1.z + v2.z + v3.z + bb.z;
    r.w = v0.w + v1.w + v2.w + v3.w + bb.w;
    ((float4*)out)[t] = r;
}

// ----------------------------------------------------------------------------
extern "C" void kernel_launch(void* const* d_in, const int* in_sizes, int n_in,
                              void* d_out, int out_size)
{
    const float* slots = (const float*)d_in[0];
    const float* w1    = (const float*)d_in[1];
    const float* b1    = (const float*)d_in[2];
    const float* w2    = (const float*)d_in[3];
    const float* b2    = (const float*)d_in[4];
    const int*   idx   = (const int*)d_in[5];
    float* out = (float*)d_out;

    group_kernel<<<1, 1024>>>(idx);
    gemm1_kernel<<<dim3(8, NEXP), 128>>>(slots, w1, b1);
    gemm2_kernel<<<dim3(8, NEXP), 128>>>(w2);
    reduce_kernel<<<256, 256>>>(b2, out);
}